// round 15
// baseline (speedup 1.0000x reference)
#include <cuda_runtime.h>
#include <cuda_bf16.h>

// Problem constants (fixed by setup_inputs):
//   x: [B=2, C=3, D=128, H=160, W=160] float32, num_steps = 6
#define BB    2
#define DD    128
#define HH    160
#define WW    160
#define PLANE (DD * HH * WW)          // 3,276,800 voxels per (batch) volume
#define NVOX  (BB * PLANE)

// Interleaved ping-pong scratch: float4 per voxel = (flow_d, flow_h, flow_w, 0).
// Batches processed sequentially so the active set (~105 MB) mostly fits L2.
__device__ float4 g_bufA[NVOX];
__device__ float4 g_bufB[NVOX];

__device__ __forceinline__ int clampi(int v, int lo, int hi) {
    return min(max(v, lo), hi);
}

// ---------------------------------------------------------------------------
// K1: fused steps 1+2 (one batch): planar x -> interleaved v2.
//   v0(y) = s*x(y); v1(y) = v0(y) + v0(q0(y)); v2(p) = v1(p) + v1(q1(p)).
// Breadth-first: all 4 voxels advance one gather-level at a time, so each
// level has 12 independent scalar loads in flight.
// ---------------------------------------------------------------------------
__global__ __launch_bounds__(256) void sq_fuse12(const float* __restrict__ xb,
                                                 float4* __restrict__ db,
                                                 float s) {
    const int W4 = WW / 4;
    int idx = blockIdx.x * blockDim.x + threadIdx.x;   // grid covers DD*HH*W4
    int w4 = idx % W4;
    int t  = idx / W4;
    int h  = t % HH;
    int d  = t / HH;

    const int p = (d * HH + h) * WW + w4 * 4;

    float4 f0 = *reinterpret_cast<const float4*>(xb + p);              // d-flow
    float4 f1 = *reinterpret_cast<const float4*>(xb + p + PLANE);      // h-flow
    float4 f2 = *reinterpret_cast<const float4*>(xb + p + 2 * PLANE);  // w-flow

    float v0d[4] = {s * f0.x, s * f0.y, s * f0.z, s * f0.w};
    float v0h[4] = {s * f1.x, s * f1.y, s * f1.z, s * f1.w};
    float v0w[4] = {s * f2.x, s * f2.y, s * f2.z, s * f2.w};

    // ---- level A: q0(p), 12 loads batched ----
    int qa[4];
#pragma unroll
    for (int j = 0; j < 4; ++j) {
        const int w = w4 * 4 + j;
        int a_d = clampi(__float2int_rn((float)d + v0d[j]), 0, DD - 1);
        int a_h = clampi(__float2int_rn((float)h + v0h[j]), 0, HH - 1);
        int a_w = clampi(__float2int_rn((float)w + v0w[j]), 0, WW - 1);
        qa[j] = (a_d * HH + a_h) * WW + a_w;
    }
    float gad[4], gah[4], gaw[4];
#pragma unroll
    for (int j = 0; j < 4; ++j) {
        gad[j] = xb[qa[j]];
        gah[j] = xb[qa[j] + PLANE];
        gaw[j] = xb[qa[j] + 2 * PLANE];
    }

    // ---- v1(p); level B: q1(p), 12 loads batched ----
    float v1pd[4], v1ph[4], v1pw[4];
    int bd[4], bh[4], bw[4], qb[4];
#pragma unroll
    for (int j = 0; j < 4; ++j) {
        const int w = w4 * 4 + j;
        v1pd[j] = v0d[j] + s * gad[j];
        v1ph[j] = v0h[j] + s * gah[j];
        v1pw[j] = v0w[j] + s * gaw[j];
        bd[j] = clampi(__float2int_rn((float)d + v1pd[j]), 0, DD - 1);
        bh[j] = clampi(__float2int_rn((float)h + v1ph[j]), 0, HH - 1);
        bw[j] = clampi(__float2int_rn((float)w + v1pw[j]), 0, WW - 1);
        qb[j] = (bd[j] * HH + bh[j]) * WW + bw[j];
    }
    float u0d[4], u0h[4], u0w[4];
#pragma unroll
    for (int j = 0; j < 4; ++j) {
        u0d[j] = s * xb[qb[j]];
        u0h[j] = s * xb[qb[j] + PLANE];
        u0w[j] = s * xb[qb[j] + 2 * PLANE];
    }

    // ---- level C: q0(q1), 12 loads batched ----
    int qc[4];
#pragma unroll
    for (int j = 0; j < 4; ++j) {
        int c_d = clampi(__float2int_rn((float)bd[j] + u0d[j]), 0, DD - 1);
        int c_h = clampi(__float2int_rn((float)bh[j] + u0h[j]), 0, HH - 1);
        int c_w = clampi(__float2int_rn((float)bw[j] + u0w[j]), 0, WW - 1);
        qc[j] = (c_d * HH + c_h) * WW + c_w;
    }
    float gcd[4], gch[4], gcw[4];
#pragma unroll
    for (int j = 0; j < 4; ++j) {
        gcd[j] = xb[qc[j]];
        gch[j] = xb[qc[j] + PLANE];
        gcw[j] = xb[qc[j] + 2 * PLANE];
    }

    // ---- combine: v2(p) = v1(p) + (v0(q1) + v0(q0(q1))) ----
#pragma unroll
    for (int j = 0; j < 4; ++j) {
        float v1qd = u0d[j] + s * gcd[j];
        float v1qh = u0h[j] + s * gch[j];
        float v1qw = u0w[j] + s * gcw[j];
        db[p + j] = make_float4(v1pd[j] + v1qd, v1ph[j] + v1qh, v1pw[j] + v1qw, 0.0f);
    }
}

// ---------------------------------------------------------------------------
// K2: fused steps 3+4 (one batch): interleaved v2 -> interleaved v4.
//   v3(y) = v2(y) + v2(q2(y));  v4(p) = v3(p) + v3(q3(p)),
//   with v3(q3) = v2(q3) + v2(q2(q3)) recomputed.
// 4 voxels/thread, warp-contiguous, breadth-first levels (MLP=4 per level).
// PLANE = 3200 blocks * 1024 voxels exactly.
// ---------------------------------------------------------------------------
__global__ __launch_bounds__(256) void sq_fuse34(const float4* __restrict__ src,
                                                 float4* __restrict__ dst) {
    const int lane = threadIdx.x & 31;
    const int warp = threadIdx.x >> 5;
    const int base = blockIdx.x * 1024 + warp * 128 + lane;  // in [0, PLANE)

    int wv[4], hv[4], dv[4];
    float4 a[4];
#pragma unroll
    for (int k = 0; k < 4; ++k) a[k] = src[base + k * 32];
#pragma unroll
    for (int k = 0; k < 4; ++k) {
        const int v = base + k * 32;
        wv[k] = v % WW;  int t = v / WW;
        hv[k] = t % HH;  dv[k] = t / HH;
    }

    // level 1: v2(q2(p))
    int q1[4];
#pragma unroll
    for (int k = 0; k < 4; ++k) {
        int id = clampi(__float2int_rn((float)dv[k] + a[k].x), 0, DD - 1);
        int ih = clampi(__float2int_rn((float)hv[k] + a[k].y), 0, HH - 1);
        int iw = clampi(__float2int_rn((float)wv[k] + a[k].z), 0, WW - 1);
        q1[k] = (id * HH + ih) * WW + iw;
    }
    float4 g1[4];
#pragma unroll
    for (int k = 0; k < 4; ++k) g1[k] = src[q1[k]];

    // v3(p); level 2: v2(q3)
    float v3d[4], v3h[4], v3w[4];
    int jd[4], jh[4], jw[4], q2[4];
#pragma unroll
    for (int k = 0; k < 4; ++k) {
        v3d[k] = a[k].x + g1[k].x;
        v3h[k] = a[k].y + g1[k].y;
        v3w[k] = a[k].z + g1[k].z;
        jd[k] = clampi(__float2int_rn((float)dv[k] + v3d[k]), 0, DD - 1);
        jh[k] = clampi(__float2int_rn((float)hv[k] + v3h[k]), 0, HH - 1);
        jw[k] = clampi(__float2int_rn((float)wv[k] + v3w[k]), 0, WW - 1);
        q2[k] = (jd[k] * HH + jh[k]) * WW + jw[k];
    }
    float4 b[4];
#pragma unroll
    for (int k = 0; k < 4; ++k) b[k] = src[q2[k]];

    // level 3: v2(q2(q3))
    int q3[4];
#pragma unroll
    for (int k = 0; k < 4; ++k) {
        int kd = clampi(__float2int_rn((float)jd[k] + b[k].x), 0, DD - 1);
        int kh = clampi(__float2int_rn((float)jh[k] + b[k].y), 0, HH - 1);
        int kw = clampi(__float2int_rn((float)jw[k] + b[k].z), 0, WW - 1);
        q3[k] = (kd * HH + kh) * WW + kw;
    }
    float4 g2[4];
#pragma unroll
    for (int k = 0; k < 4; ++k) g2[k] = src[q3[k]];

#pragma unroll
    for (int k = 0; k < 4; ++k) {
        float v3qd = b[k].x + g2[k].x;
        float v3qh = b[k].y + g2[k].y;
        float v3qw = b[k].z + g2[k].z;
        dst[base + k * 32] =
            make_float4(v3d[k] + v3qd, v3h[k] + v3qh, v3w[k] + v3qw, 0.0f);
    }
}

// ---------------------------------------------------------------------------
// K3: fused steps 5+6 (one batch): interleaved v4 -> planar out v6.
//   v5(y) = v4(y) + v4(q4(y));  v6(p) = v5(p) + v5(q5(p)),
//   with v5(q5) = v4(q5) + v4(q4(q5)) recomputed.
// 4 consecutive-W voxels/thread, breadth-first levels, coalesced planar stores.
// ---------------------------------------------------------------------------
__global__ __launch_bounds__(256) void sq_fuse56last(const float4* __restrict__ sb,
                                                     float* __restrict__ ob) {
    const int W4 = WW / 4;
    int idx = blockIdx.x * blockDim.x + threadIdx.x;
    int w4 = idx % W4;
    int t  = idx / W4;
    int h  = t % HH;
    int d  = t / HH;

    const int p = (d * HH + h) * WW + w4 * 4;

    float4 a[4];
#pragma unroll
    for (int j = 0; j < 4; ++j) a[j] = sb[p + j];

    // level 1: v4(q4(p))
    int q1[4];
#pragma unroll
    for (int j = 0; j < 4; ++j) {
        const int w = w4 * 4 + j;
        int id = clampi(__float2int_rn((float)d + a[j].x), 0, DD - 1);
        int ih = clampi(__float2int_rn((float)h + a[j].y), 0, HH - 1);
        int iw = clampi(__float2int_rn((float)w + a[j].z), 0, WW - 1);
        q1[j] = (id * HH + ih) * WW + iw;
    }
    float4 g1[4];
#pragma unroll
    for (int j = 0; j < 4; ++j) g1[j] = sb[q1[j]];

    // v5(p); level 2: v4(q5)
    float v5d[4], v5h[4], v5w[4];
    int jd[4], jh[4], jw[4], q2[4];
#pragma unroll
    for (int j = 0; j < 4; ++j) {
        const int w = w4 * 4 + j;
        v5d[j] = a[j].x + g1[j].x;
        v5h[j] = a[j].y + g1[j].y;
        v5w[j] = a[j].z + g1[j].z;
        jd[j] = clampi(__float2int_rn((float)d + v5d[j]), 0, DD - 1);
        jh[j] = clampi(__float2int_rn((float)h + v5h[j]), 0, HH - 1);
        jw[j] = clampi(__float2int_rn((float)w + v5w[j]), 0, WW - 1);
        q2[j] = (jd[j] * HH + jh[j]) * WW + jw[j];
    }
    float4 b[4];
#pragma unroll
    for (int j = 0; j < 4; ++j) b[j] = sb[q2[j]];

    // level 3: v4(q4(q5))
    int q3[4];
#pragma unroll
    for (int j = 0; j < 4; ++j) {
        int kd = clampi(__float2int_rn((float)jd[j] + b[j].x), 0, DD - 1);
        int kh = clampi(__float2int_rn((float)jh[j] + b[j].y), 0, HH - 1);
        int kw = clampi(__float2int_rn((float)jw[j] + b[j].z), 0, WW - 1);
        q3[j] = (kd * HH + kh) * WW + kw;
    }
    float4 g2[4];
#pragma unroll
    for (int j = 0; j < 4; ++j) g2[j] = sb[q3[j]];

    float o0[4], o1[4], o2[4];
#pragma unroll
    for (int j = 0; j < 4; ++j) {
        float v5qd = b[j].x + g2[j].x;
        float v5qh = b[j].y + g2[j].y;
        float v5qw = b[j].z + g2[j].z;
        o0[j] = v5d[j] + v5qd;
        o1[j] = v5h[j] + v5qh;
        o2[j] = v5w[j] + v5qw;
    }

    *reinterpret_cast<float4*>(ob + p)             = make_float4(o0[0], o0[1], o0[2], o0[3]);
    *reinterpret_cast<float4*>(ob + p + PLANE)     = make_float4(o1[0], o1[1], o1[2], o1[3]);
    *reinterpret_cast<float4*>(ob + p + 2 * PLANE) = make_float4(o2[0], o2[1], o2[2], o2[3]);
}

extern "C" void kernel_launch(void* const* d_in, const int* in_sizes, int n_in,
                              void* d_out, int out_size) {
    const float* x   = (const float*)d_in[0];
    float*       out = (float*)d_out;

    float4 *A = nullptr, *B = nullptr;
    cudaGetSymbolAddress((void**)&A, g_bufA);
    cudaGetSymbolAddress((void**)&B, g_bufB);

    const int tpb  = 256;
    const int blkQ = (DD * HH * (WW / 4)) / tpb;   // 3200 blocks (4 voxels/thread)
    const int blkM = PLANE / 1024;                 // 3200 blocks (4 voxels/thread)

    const float s0 = 1.0f / 64.0f;                 // 1 / 2^num_steps (num_steps = 6)

    // Batch-sequential: keeps the per-batch working set mostly L2-resident.
    for (int b = 0; b < BB; ++b) {
        const float* xb = x   + (size_t)b * 3 * PLANE;
        float*       ob = out + (size_t)b * 3 * PLANE;
        float4*      Ab = A   + (size_t)b * PLANE;
        float4*      Bb = B   + (size_t)b * PLANE;

        sq_fuse12    <<<blkQ, tpb>>>(xb, Ab, s0);  // steps 1+2: x  -> v2
        sq_fuse34    <<<blkM, tpb>>>(Ab, Bb);      // steps 3+4: v2 -> v4
        sq_fuse56last<<<blkQ, tpb>>>(Bb, ob);      // steps 5+6: v4 -> out
    }
}